// round 10
// baseline (speedup 1.0000x reference)
#include <cuda_runtime.h>
#include <cstdint>

#define BB 8
#define NN 4096
#define SS 1024
#define NSAMP 32
#define CIN 64
#define CMLP 128
#define COUT 256

// fps_prep block layout: 0..7 fps, 8..40 wfuse, 41..56 clear
#define NB_FPS   8
#define B_WFUSE  8
#define B_CLEAR  41
#define GRID_FP  57

// packed f32x2 helpers (Blackwell FFMA2 path — PTX only)
#define ADD_F32X2(out, a, b) \
    asm("add.rn.f32x2 %0, %1, %2;" : "=l"(out) : "l"(a), "l"(b))
#define MUL_F32X2(out, a, b) \
    asm("mul.rn.f32x2 %0, %1, %2;" : "=l"(out) : "l"(a), "l"(b))
#define FMA_F32X2(out, a, b, c) \
    asm("fma.rn.f32x2 %0, %1, %2, %3;" : "=l"(out) : "l"(a), "l"(b), "l"(c))
#define PACK_F32X2(out, lo, hi) \
    asm("mov.b64 %0, {%1, %2};" : "=l"(out) : "f"(lo), "f"(hi))
#define UNPACK_F32X2(lo, hi, in) \
    asm("mov.b64 {%0, %1}, %2;" : "=f"(lo), "=f"(hi) : "l"(in))

// ---------------- scratch (device globals; no allocation) ----------------
__device__ float d_g[BB * NN * COUT];     // fused-MLP output per point  (33.5 MB)
__device__ float d_Wf[CIN * COUT];        // W1 @ Wc
__device__ float d_bf[COUT];              // b1 @ Wc + bc
__device__ float d_newxyz[BB * SS * 3];   // FPS-sampled centers
__device__ int   d_gidx[BB * SS * NSAMP]; // ball-query groups
__device__ int   d_cnt[BB * NN];          // per-point gather multiplicity (BN weights)
__device__ float d_sum[COUT];
__device__ float d_sumsq[COUT];

// ============ LAUNCH 1: fps (blocks 0..7, round-4 validated body) + prep ============
// No inter-block communication; the launch boundary is the only synchronization.
__global__ void __launch_bounds__(512, 1) fps_prep_kernel(
        const float* __restrict__ xyz,
        const float* __restrict__ W1, const float* __restrict__ b1,
        const float* __restrict__ Wc, const float* __restrict__ bc) {
    __shared__ unsigned svh[2][16];
    __shared__ unsigned svl[2][16];
    const int bid = blockIdx.x;
    const int tid = threadIdx.x;

    if (bid >= NB_FPS) {
        if (bid < B_CLEAR) {
            // WFUSE: Wf = W1@Wc, bf = b1@Wc + bc   (33 blocks x 512 = 16896 >= 16640)
            int idx = (bid - B_WFUSE) * 512 + tid;
            if (idx < (CIN + 1) * COUT) {
                int k = idx >> 8, c = idx & 255;
                if (k < CIN) {
                    float acc = 0.f;
                    for (int m = 0; m < CMLP; m++) acc += W1[k * CMLP + m] * Wc[m * COUT + c];
                    d_Wf[k * COUT + c] = acc;
                } else {
                    float acc = bc[c];
                    for (int m = 0; m < CMLP; m++) acc += b1[m] * Wc[m * COUT + c];
                    d_bf[c] = acc;
                }
            }
        } else {
            // CLEAR: cnt + stats accumulators  (16 blocks x 512 = 8192)
            int g = (bid - B_CLEAR) * 512 + tid;
#pragma unroll
            for (int r = 0; r < 4; r++) d_cnt[g + r * 8192] = 0;
            if (g < COUT) { d_sum[g] = 0.f; d_sumsq[g] = 0.f; }
        }
        return;
    }

    // -------- FPS (exact round-4 body: 415us-validated) --------
    // 512 threads, 8 pts/thread as 4 packed f32x2 pairs; __ldg loads; serial
    // if-chain thread argmax; REDUX warp argmax; double-buffered partials.
    const int b = bid;
    const float* xb = xyz + (size_t)b * NN * 3;

    unsigned long long px2[4], py2[4], pz2[4];
    float dmin[8];
#pragma unroll
    for (int p = 0; p < 4; p++) {
        int i0 = tid + ((2 * p) << 9);
        int i1 = tid + ((2 * p + 1) << 9);
        float x0 = __ldg(xb + i0 * 3 + 0), x1 = __ldg(xb + i1 * 3 + 0);
        float y0 = __ldg(xb + i0 * 3 + 1), y1 = __ldg(xb + i1 * 3 + 1);
        float z0 = __ldg(xb + i0 * 3 + 2), z1 = __ldg(xb + i1 * 3 + 2);
        PACK_F32X2(px2[p], x0, x1);
        PACK_F32X2(py2[p], y0, y1);
        PACK_F32X2(pz2[p], z0, z1);
        dmin[2 * p] = 1e10f; dmin[2 * p + 1] = 1e10f;
    }

    int far = 0;
    const int lane = tid & 31, w = tid >> 5;

    for (int it = 0; it < SS; it++) {
        float cx = __ldg(xb + far * 3 + 0);
        float cy = __ldg(xb + far * 3 + 1);
        float cz = __ldg(xb + far * 3 + 2);
        if (tid == 0) {
            float* nx = d_newxyz + ((size_t)b * SS + it) * 3;
            nx[0] = cx; nx[1] = cy; nx[2] = cz;
        }
        if (it == SS - 1) break;   // last step's argmax is unused by reference

        unsigned long long ncx2, ncy2, ncz2;
        {
            float nx = -cx, ny = -cy, nz = -cz;
            PACK_F32X2(ncx2, nx, nx);
            PACK_F32X2(ncy2, ny, ny);
            PACK_F32X2(ncz2, nz, nz);
        }

        float bv = -1.f; int bi = 0;
#pragma unroll
        for (int p = 0; p < 4; p++) {
            unsigned long long dx2, dy2, dz2, dd2;
            ADD_F32X2(dx2, px2[p], ncx2);            // px - cx   (same rounding)
            ADD_F32X2(dy2, py2[p], ncy2);
            ADD_F32X2(dz2, pz2[p], ncz2);
            MUL_F32X2(dd2, dx2, dx2);                // dx*dx
            FMA_F32X2(dd2, dy2, dy2, dd2);           // + dy*dy
            FMA_F32X2(dd2, dz2, dz2, dd2);           // + dz*dz  (same association)
            float d0, d1;
            UNPACK_F32X2(d0, d1, dd2);
            float m0 = fminf(dmin[2 * p], d0);       dmin[2 * p] = m0;
            float m1 = fminf(dmin[2 * p + 1], d1);   dmin[2 * p + 1] = m1;
            if (m0 > bv) { bv = m0; bi = tid + ((2 * p) << 9); }      // strict >
            if (m1 > bv) { bv = m1; bi = tid + ((2 * p + 1) << 9); }  // lowest idx
        }
        // warp argmax: dist>=0 so float bits compare as unsigned; ~idx max = min idx
        unsigned hv   = __float_as_uint(bv);
        unsigned m    = __reduce_max_sync(0xffffffffu, hv);
        unsigned cand = (hv == m) ? ~(unsigned)bi : 0u;
        unsigned l2   = __reduce_max_sync(0xffffffffu, cand);

        int buf = it & 1;
        if (lane == 0) { svh[buf][w] = m; svl[buf][w] = l2; }
        __syncthreads();

        unsigned hi = (lane < 16) ? svh[buf][lane] : 0u;
        unsigned lo = (lane < 16) ? svl[buf][lane] : 0u;
        unsigned M  = __reduce_max_sync(0xffffffffu, hi);
        unsigned c2 = (hi == M) ? lo : 0u;
        unsigned L  = __reduce_max_sync(0xffffffffu, c2);
        far = (int)~L;
    }
}

// ---------------- ball query: one warp per center, ordered scan + early exit ----------------
__global__ void __launch_bounds__(512) ballq_kernel(const float* __restrict__ xyz) {
    extern __shared__ float sm[];
    float* xs = sm;
    float* ys = sm + NN;
    float* zs = sm + 2 * NN;

    const int b = blockIdx.y;
    const float* xb = xyz + (size_t)b * NN * 3;
    for (int k = threadIdx.x; k < NN * 3; k += 512) {
        float v = xb[k];
        int i = k / 3, c = k - 3 * i;
        if (c == 0) xs[i] = v; else if (c == 1) ys[i] = v; else zs[i] = v;
    }
    __syncthreads();

    const int warp = threadIdx.x >> 5, lane = threadIdx.x & 31;
    const int s = blockIdx.x * 16 + warp;
    const float* cp = d_newxyz + ((size_t)b * SS + s) * 3;
    const float cx = __ldg(cp + 0), cy = __ldg(cp + 1), cz = __ldg(cp + 2);
    const int base = (b * SS + s) * NSAMP;
    const float r2 = 0.15f * 0.15f;

    int count = 0, first = 0;
    for (int ci = 0; ci < NN / 32; ci++) {
        int i = ci * 32 + lane;
        float dx = cx - xs[i], dy = cy - ys[i], dz = cz - zs[i];
        float d = dx * dx + dy * dy + dz * dz;
        bool hit = (d <= r2);
        unsigned m = __ballot_sync(0xffffffffu, hit);
        if (m) {
            if (count == 0) first = __shfl_sync(0xffffffffu, i, __ffs(m) - 1);
            int nh   = __popc(m);
            int take = min(nh, NSAMP - count);
            int pos  = __popc(m & ((1u << lane) - 1u));
            if (hit && pos < take) {
                d_gidx[base + count + pos] = i;
                atomicAdd(&d_cnt[b * NN + i], 1);
            }
            count += take;
            if (count >= NSAMP) break;
        }
    }
    if (lane >= count) {   // pad with first in-radius index (center guarantees >=1 hit)
        d_gidx[base + lane] = first;
        atomicAdd(&d_cnt[b * NN + first], 1);
    }
}

// ---------------- g = points @ Wf + bf, with fused BN-stats epilogue ----------------
__global__ void __launch_bounds__(256, 4) gemm_stats_kernel(const float* __restrict__ points) {
    __shared__ float4 sW[CIN * 32];   // 32KB: this block's 128 cols
    __shared__ float  sP[64 * CIN];   // 16KB: points tile (reused as reduce buffer)

    const int row0 = blockIdx.x * 64;
    const int cb   = blockIdx.y * 128;

    const float4* Wq = (const float4*)d_Wf;          // 64 quads per k-row
    for (int t = threadIdx.x; t < CIN * 32; t += 256) {
        int k = t >> 5, q = t & 31;
        sW[t] = Wq[k * 64 + (cb >> 2) + q];
    }
    const float4* Pq = (const float4*)(points + (size_t)row0 * CIN);
    float4* sPq = (float4*)sP;
    for (int t = threadIdx.x; t < 64 * (CIN / 4); t += 256) sPq[t] = Pq[t];
    __syncthreads();

    const int rg = threadIdx.x >> 5;   // warp 0..7 -> rows rg*8..rg*8+7
    const int cg = threadIdx.x & 31;   // lane -> cols cb + cg*4 .. +3
    const int r0 = rg * 8;

    unsigned long long acc2[8][2];
    {
        float4 bias = *(const float4*)(d_bf + cb + cg * 4);
#pragma unroll
        for (int i = 0; i < 8; i++) {
            PACK_F32X2(acc2[i][0], bias.x, bias.y);
            PACK_F32X2(acc2[i][1], bias.z, bias.w);
        }
    }

#pragma unroll
    for (int k = 0; k < CIN; k += 4) {
        float pr[8][4];
#pragma unroll
        for (int i = 0; i < 8; i++) {
            float4 t = *(const float4*)&sP[(r0 + i) * CIN + k];   // warp broadcast
            pr[i][0] = t.x; pr[i][1] = t.y; pr[i][2] = t.z; pr[i][3] = t.w;
        }
#pragma unroll
        for (int kk = 0; kk < 4; kk++) {
            const unsigned long long* wv =
                (const unsigned long long*)&sW[(k + kk) * 32 + cg];
            unsigned long long w01 = wv[0], w23 = wv[1];
#pragma unroll
            for (int i = 0; i < 8; i++) {
                unsigned long long p2;
                PACK_F32X2(p2, pr[i][kk], pr[i][kk]);
                FMA_F32X2(acc2[i][0], p2, w01, acc2[i][0]);
                FMA_F32X2(acc2[i][1], p2, w23, acc2[i][1]);
            }
        }
    }

    // store + per-thread weighted stats
    float s[4] = {0.f, 0.f, 0.f, 0.f}, q[4] = {0.f, 0.f, 0.f, 0.f};
#pragma unroll
    for (int i = 0; i < 8; i++) {
        float a0, a1, a2, a3;
        UNPACK_F32X2(a0, a1, acc2[i][0]);
        UNPACK_F32X2(a2, a3, acc2[i][1]);
        float* op = d_g + (size_t)(row0 + r0 + i) * COUT + cb + cg * 4;
        *(float4*)op = make_float4(a0, a1, a2, a3);
        float wi = (float)__ldg(&d_cnt[row0 + r0 + i]);
        float t0 = wi * a0, t1 = wi * a1, t2 = wi * a2, t3 = wi * a3;
        s[0] += t0; q[0] += t0 * a0;
        s[1] += t1; q[1] += t1 * a1;
        s[2] += t2; q[2] += t2 * a2;
        s[3] += t3; q[3] += t3 * a3;
    }

    // cross-warp reduce in smem (overlay on sP), then 256 atomics by warp 0
    __syncthreads();                      // sP reads in k-loop are done
    float2* red = (float2*)sP;            // [8][128] float2 = 8KB
#pragma unroll
    for (int c = 0; c < 4; c++) red[rg * 128 + cg * 4 + c] = make_float2(s[c], q[c]);
    __syncthreads();
    if (rg == 0) {
#pragma unroll
        for (int c = 0; c < 4; c++) {
            float ss = 0.f, qq = 0.f;
#pragma unroll
            for (int r = 0; r < 8; r++) {
                float2 t = red[r * 128 + cg * 4 + c];
                ss += t.x; qq += t.y;
            }
            atomicAdd(&d_sum[cb + cg * 4 + c], ss);
            atomicAdd(&d_sumsq[cb + cg * 4 + c], qq);
        }
    }
}

// ---------------- gather + BN + ReLU + max-pool (BN affine recomputed per block) ------
__global__ void __launch_bounds__(256) final_kernel(
        const float* __restrict__ gamma, const float* __restrict__ beta,
        float* __restrict__ out) {
    const int b = blockIdx.y, s = blockIdx.x, c = threadIdx.x;
    __shared__ int idx[NSAMP];
    if (c < NSAMP) idx[c] = d_gidx[(b * SS + s) * NSAMP + c];
    __syncthreads();
    const float* gb = d_g + (size_t)b * NN * COUT + c;
    float mx = -1e30f, mn = 1e30f;
#pragma unroll
    for (int n = 0; n < NSAMP; n++) {
        float v = gb[(size_t)idx[n] * COUT];
        mx = fmaxf(mx, v);
        mn = fminf(mn, v);
    }
    const float M = (float)(BB * SS * NSAMP);
    float mean = d_sum[c] / M;
    float var  = fmaxf(d_sumsq[c] / M - mean * mean, 0.f);
    float a    = gamma[c] / sqrtf(var + 1e-5f);
    float bb2  = beta[c] - mean * a;
    float m = (a >= 0.f) ? mx : mn;     // relu(a*max+b) = max relu(a*h+b), monotone
    out[((size_t)(b * SS + s)) * COUT + c] = fmaxf(a * m + bb2, 0.f);
}

// ---------------- launch (single stream; graph-capture safe) ----------------
extern "C" void kernel_launch(void* const* d_in, const int* in_sizes, int n_in,
                              void* d_out, int out_size) {
    const float* xyz    = (const float*)d_in[0];
    // d_in[1] = t : unused by reference
    const float* points = (const float*)d_in[2];
    const float* W1     = (const float*)d_in[3];
    const float* b1     = (const float*)d_in[4];
    const float* Wc     = (const float*)d_in[5];
    const float* bc     = (const float*)d_in[6];
    const float* gamma  = (const float*)d_in[7];
    const float* beta   = (const float*)d_in[8];
    float* out = (float*)d_out;

    fps_prep_kernel<<<GRID_FP, 512>>>(xyz, W1, b1, Wc, bc);
    ballq_kernel<<<dim3(SS / 16, BB), 512, NN * 3 * sizeof(float)>>>(xyz);
    gemm_stats_kernel<<<dim3((BB * NN) / 64, 2), 256>>>(points);
    final_kernel<<<dim3(SS, BB), 256>>>(gamma, beta, out);
}

// round 11
// speedup vs baseline: 1.6232x; 1.6232x over previous
#include <cuda_runtime.h>
#include <cstdint>

#define BB 8
#define NN 4096
#define SS 1024
#define NSAMP 32
#define CIN 64
#define CMLP 128
#define COUT 256

// fps_prep block layout: 0..7 fps, 8..40 wfuse, 41..56 clear
#define NB_FPS   8
#define B_WFUSE  8
#define B_CLEAR  41
#define GRID_FP  57

// ballq_gemm block layout: 0..511 ballq, 512..1535 gemm
#define NB_BALLQ 512
#define GRID_BG  1536

// packed f32x2 helpers (Blackwell FFMA2 path — PTX only)
#define ADD_F32X2(out, a, b) \
    asm("add.rn.f32x2 %0, %1, %2;" : "=l"(out) : "l"(a), "l"(b))
#define MUL_F32X2(out, a, b) \
    asm("mul.rn.f32x2 %0, %1, %2;" : "=l"(out) : "l"(a), "l"(b))
#define FMA_F32X2(out, a, b, c) \
    asm("fma.rn.f32x2 %0, %1, %2, %3;" : "=l"(out) : "l"(a), "l"(b), "l"(c))
#define PACK_F32X2(out, lo, hi) \
    asm("mov.b64 %0, {%1, %2};" : "=l"(out) : "f"(lo), "f"(hi))
#define UNPACK_F32X2(lo, hi, in) \
    asm("mov.b64 {%0, %1}, %2;" : "=f"(lo), "=f"(hi) : "l"(in))

// ---------------- scratch (device globals; no allocation) ----------------
__device__ float d_g[BB * NN * COUT];     // fused-MLP output per point  (33.5 MB)
__device__ float d_Wf[CIN * COUT];        // W1 @ Wc
__device__ float d_bf[COUT];              // b1 @ Wc + bc
__device__ float d_newxyz[BB * SS * 3];   // FPS-sampled centers
__device__ int   d_gidx[BB * SS * NSAMP]; // ball-query groups
__device__ int   d_cnt[BB * NN];          // per-point gather multiplicity (BN weights)
__device__ float d_sum[COUT];
__device__ float d_sumsq[COUT];

// ============ LAUNCH 1: fps (blocks 0..7, round-4 validated body) + prep ============
// No inter-block communication; the launch boundary is the only synchronization.
__global__ void __launch_bounds__(512, 1) fps_prep_kernel(
        const float* __restrict__ xyz,
        const float* __restrict__ W1, const float* __restrict__ b1,
        const float* __restrict__ Wc, const float* __restrict__ bc) {
    __shared__ unsigned svh[2][16];
    __shared__ unsigned svl[2][16];
    const int bid = blockIdx.x;
    const int tid = threadIdx.x;

    if (bid >= NB_FPS) {
        if (bid < B_CLEAR) {
            // WFUSE: Wf = W1@Wc, bf = b1@Wc + bc   (33 blocks x 512 = 16896 >= 16640)
            int idx = (bid - B_WFUSE) * 512 + tid;
            if (idx < (CIN + 1) * COUT) {
                int k = idx >> 8, c = idx & 255;
                if (k < CIN) {
                    float acc = 0.f;
                    for (int m = 0; m < CMLP; m++) acc += W1[k * CMLP + m] * Wc[m * COUT + c];
                    d_Wf[k * COUT + c] = acc;
                } else {
                    float acc = bc[c];
                    for (int m = 0; m < CMLP; m++) acc += b1[m] * Wc[m * COUT + c];
                    d_bf[c] = acc;
                }
            }
        } else {
            // CLEAR: cnt + stats accumulators  (16 blocks x 512 = 8192)
            int g = (bid - B_CLEAR) * 512 + tid;
#pragma unroll
            for (int r = 0; r < 4; r++) d_cnt[g + r * 8192] = 0;
            if (g < COUT) { d_sum[g] = 0.f; d_sumsq[g] = 0.f; }
        }
        return;
    }

    // -------- FPS (round-4 validated body) --------
    const int b = bid;
    const float* xb = xyz + (size_t)b * NN * 3;

    unsigned long long px2[4], py2[4], pz2[4];
    float dmin[8];
#pragma unroll
    for (int p = 0; p < 4; p++) {
        int i0 = tid + ((2 * p) << 9);
        int i1 = tid + ((2 * p + 1) << 9);
        float x0 = __ldg(xb + i0 * 3 + 0), x1 = __ldg(xb + i1 * 3 + 0);
        float y0 = __ldg(xb + i0 * 3 + 1), y1 = __ldg(xb + i1 * 3 + 1);
        float z0 = __ldg(xb + i0 * 3 + 2), z1 = __ldg(xb + i1 * 3 + 2);
        PACK_F32X2(px2[p], x0, x1);
        PACK_F32X2(py2[p], y0, y1);
        PACK_F32X2(pz2[p], z0, z1);
        dmin[2 * p] = 1e10f; dmin[2 * p + 1] = 1e10f;
    }

    int far = 0;
    const int lane = tid & 31, w = tid >> 5;

    for (int it = 0; it < SS; it++) {
        float cx = __ldg(xb + far * 3 + 0);
        float cy = __ldg(xb + far * 3 + 1);
        float cz = __ldg(xb + far * 3 + 2);
        if (tid == 0) {
            float* nx = d_newxyz + ((size_t)b * SS + it) * 3;
            nx[0] = cx; nx[1] = cy; nx[2] = cz;
        }
        if (it == SS - 1) break;   // last step's argmax is unused by reference

        unsigned long long ncx2, ncy2, ncz2;
        {
            float nx = -cx, ny = -cy, nz = -cz;
            PACK_F32X2(ncx2, nx, nx);
            PACK_F32X2(ncy2, ny, ny);
            PACK_F32X2(ncz2, nz, nz);
        }

        float bv = -1.f; int bi = 0;
#pragma unroll
        for (int p = 0; p < 4; p++) {
            unsigned long long dx2, dy2, dz2, dd2;
            ADD_F32X2(dx2, px2[p], ncx2);            // px - cx   (same rounding)
            ADD_F32X2(dy2, py2[p], ncy2);
            ADD_F32X2(dz2, pz2[p], ncz2);
            MUL_F32X2(dd2, dx2, dx2);                // dx*dx
            FMA_F32X2(dd2, dy2, dy2, dd2);           // + dy*dy
            FMA_F32X2(dd2, dz2, dz2, dd2);           // + dz*dz  (same association)
            float d0, d1;
            UNPACK_F32X2(d0, d1, dd2);
            float m0 = fminf(dmin[2 * p], d0);       dmin[2 * p] = m0;
            float m1 = fminf(dmin[2 * p + 1], d1);   dmin[2 * p + 1] = m1;
            if (m0 > bv) { bv = m0; bi = tid + ((2 * p) << 9); }      // strict >
            if (m1 > bv) { bv = m1; bi = tid + ((2 * p + 1) << 9); }  // lowest idx
        }
        // warp argmax: dist>=0 so float bits compare as unsigned; ~idx max = min idx
        unsigned hv   = __float_as_uint(bv);
        unsigned m    = __reduce_max_sync(0xffffffffu, hv);
        unsigned cand = (hv == m) ? ~(unsigned)bi : 0u;
        unsigned l2   = __reduce_max_sync(0xffffffffu, cand);

        int buf = it & 1;
        if (lane == 0) { svh[buf][w] = m; svl[buf][w] = l2; }
        __syncthreads();

        unsigned hi = (lane < 16) ? svh[buf][lane] : 0u;
        unsigned lo = (lane < 16) ? svl[buf][lane] : 0u;
        unsigned M  = __reduce_max_sync(0xffffffffu, hi);
        unsigned c2 = (hi == M) ? lo : 0u;
        unsigned L  = __reduce_max_sync(0xffffffffu, c2);
        far = (int)~L;
    }
}

// ============ LAUNCH 2: ballq (blocks 0..511) + gemm (blocks 512..1535) ============
// Independent work: ballq writes d_gidx/d_cnt, gemm writes d_g. Both read only
// launch-1 outputs. Shared 48KB extern buffer, carved per path.
__global__ void __launch_bounds__(512) ballq_gemm_kernel(
        const float* __restrict__ xyz, const float* __restrict__ points) {
    extern __shared__ __align__(16) char SM[];
    const int bid = blockIdx.x;
    const int tid = threadIdx.x;

    if (bid < NB_BALLQ) {
        // -------- ball query: one warp per center, ordered scan + early exit ------
        float* xs = (float*)SM;
        float* ys = xs + NN;
        float* zs = ys + NN;

        const int b  = bid >> 6;            // 64 blocks per batch
        const int s0 = (bid & 63) * 16;

        const float* xb = xyz + (size_t)b * NN * 3;
        for (int k = tid; k < NN * 3; k += 512) {
            float v = xb[k];
            int i = k / 3, c = k - 3 * i;
            if (c == 0) xs[i] = v; else if (c == 1) ys[i] = v; else zs[i] = v;
        }
        __syncthreads();

        const int warp = tid >> 5, lane = tid & 31;
        const int s = s0 + warp;
        const float* cp = d_newxyz + ((size_t)b * SS + s) * 3;
        const float cx = __ldg(cp + 0), cy = __ldg(cp + 1), cz = __ldg(cp + 2);
        const int base = (b * SS + s) * NSAMP;
        const float r2 = 0.15f * 0.15f;

        int count = 0, first = 0;
        for (int ci = 0; ci < NN / 32; ci++) {
            int i = ci * 32 + lane;
            float dx = cx - xs[i], dy = cy - ys[i], dz = cz - zs[i];
            float d = dx * dx + dy * dy + dz * dz;
            bool hit = (d <= r2);
            unsigned m = __ballot_sync(0xffffffffu, hit);
            if (m) {
                if (count == 0) first = __shfl_sync(0xffffffffu, i, __ffs(m) - 1);
                int nh   = __popc(m);
                int take = min(nh, NSAMP - count);
                int pos  = __popc(m & ((1u << lane) - 1u));
                if (hit && pos < take) {
                    d_gidx[base + count + pos] = i;
                    atomicAdd(&d_cnt[b * NN + i], 1);
                }
                count += take;
                if (count >= NSAMP) break;
            }
        }
        if (lane >= count) {   // pad with first in-radius index
            d_gidx[base + lane] = first;
            atomicAdd(&d_cnt[b * NN + first], 1);
        }
        return;
    }

    // -------- GEMM: g = points @ Wf + bf (round-5 validated 512-thread body) ------
    {
        float*  sP = (float*)SM;                  // [64][64]  16KB
        float4* sW = (float4*)(SM + 16384);       // [64][32]  32KB

        const int gi   = bid - NB_BALLQ;
        const int row0 = (gi >> 1) * 64;
        const int cb   = (gi & 1) * 128;

        const float4* Pq = (const float4*)(points + (size_t)row0 * CIN);
        ((float4*)sP)[tid]       = Pq[tid];
        ((float4*)sP)[tid + 512] = Pq[tid + 512];

        const float4* Wq = (const float4*)d_Wf;   // 64 quads per k-row
#pragma unroll
        for (int t = tid; t < CIN * 32; t += 512) {
            int k = t >> 5, q = t & 31;
            sW[t] = Wq[k * 64 + (cb >> 2) + q];
        }
        __syncthreads();

        const int w = tid >> 5, lane = tid & 31;
        const int r0 = w * 4;                     // 16 warps x 4 rows = 64

        float4 acc[4];
        float4 bias = *(const float4*)(d_bf + cb + lane * 4);
#pragma unroll
        for (int i = 0; i < 4; i++) acc[i] = bias;

#pragma unroll
        for (int k = 0; k < CIN; k += 4) {
            float pr[4][4];
#pragma unroll
            for (int i = 0; i < 4; i++) {
                float4 t = *(const float4*)&sP[(r0 + i) * CIN + k];
                pr[i][0] = t.x; pr[i][1] = t.y; pr[i][2] = t.z; pr[i][3] = t.w;
            }
#pragma unroll
            for (int kk = 0; kk < 4; kk++) {
                float4 wv = sW[(k + kk) * 32 + lane];
#pragma unroll
                for (int i = 0; i < 4; i++) {
                    acc[i].x += pr[i][kk] * wv.x;
                    acc[i].y += pr[i][kk] * wv.y;
                    acc[i].z += pr[i][kk] * wv.z;
                    acc[i].w += pr[i][kk] * wv.w;
                }
            }
        }
#pragma unroll
        for (int i = 0; i < 4; i++)
            *(float4*)(d_g + (size_t)(row0 + r0 + i) * COUT + cb + lane * 4) = acc[i];
    }
}

// ---------------- BN statistics via per-point counts (round-4 validated) ----------------
__global__ void __launch_bounds__(256) stats_kernel() {
    const int c    = threadIdx.x;
    const int row0 = blockIdx.x * 128;
    __shared__ float wcnt[128];
    if (threadIdx.x < 128) wcnt[threadIdx.x] = (float)d_cnt[row0 + threadIdx.x];
    __syncthreads();
    float s = 0.f, q = 0.f;
    for (int r = 0; r < 128; r++) {
        float w = wcnt[r];
        if (w != 0.f) {
            float v = d_g[(size_t)(row0 + r) * COUT + c];
            float wvv = w * v;
            s += wvv;
            q += wvv * v;
        }
    }
    atomicAdd(&d_sum[c], s);
    atomicAdd(&d_sumsq[c], q);
}

// ---------------- gather + BN + ReLU + max-pool (BN affine recomputed per block) ------
__global__ void __launch_bounds__(256) final_kernel(
        const float* __restrict__ gamma, const float* __restrict__ beta,
        float* __restrict__ out) {
    const int b = blockIdx.y, s = blockIdx.x, c = threadIdx.x;
    __shared__ int idx[NSAMP];
    if (c < NSAMP) idx[c] = d_gidx[(b * SS + s) * NSAMP + c];
    __syncthreads();
    const float* gb = d_g + (size_t)b * NN * COUT + c;
    float mx = -1e30f, mn = 1e30f;
#pragma unroll
    for (int n = 0; n < NSAMP; n++) {
        float v = gb[(size_t)idx[n] * COUT];
        mx = fmaxf(mx, v);
        mn = fminf(mn, v);
    }
    const float M = (float)(BB * SS * NSAMP);
    float mean = d_sum[c] / M;
    float var  = fmaxf(d_sumsq[c] / M - mean * mean, 0.f);
    float a    = gamma[c] / sqrtf(var + 1e-5f);
    float bb2  = beta[c] - mean * a;
    float m = (a >= 0.f) ? mx : mn;     // relu(a*max+b) = max relu(a*h+b), monotone
    out[((size_t)(b * SS + s)) * COUT + c] = fmaxf(a * m + bb2, 0.f);
}

// ---------------- launch (single stream; graph-capture safe) ----------------
extern "C" void kernel_launch(void* const* d_in, const int* in_sizes, int n_in,
                              void* d_out, int out_size) {
    const float* xyz    = (const float*)d_in[0];
    // d_in[1] = t : unused by reference
    const float* points = (const float*)d_in[2];
    const float* W1     = (const float*)d_in[3];
    const float* b1     = (const float*)d_in[4];
    const float* Wc     = (const float*)d_in[5];
    const float* bc     = (const float*)d_in[6];
    const float* gamma  = (const float*)d_in[7];
    const float* beta   = (const float*)d_in[8];
    float* out = (float*)d_out;

    fps_prep_kernel<<<GRID_FP, 512>>>(xyz, W1, b1, Wc, bc);
    ballq_gemm_kernel<<<GRID_BG, 512, NN * 3 * sizeof(float)>>>(xyz, points);
    stats_kernel<<<(BB * NN) / 128, 256>>>();
    final_kernel<<<dim3(SS, BB), 256>>>(gamma, beta, out);
}